// round 6
// baseline (speedup 1.0000x reference)
#include <cuda_runtime.h>
#include <cstdint>

#define BATCH 4
#define SEQ   4096
#define CDIM  256
#define DDIM  32
#define TQ    128
#define TK    64
#define NT_TILES (SEQ / TK)

// ---- scratch ----
__device__ float g_q[BATCH * SEQ * DDIM];
__device__ float g_k[BATCH * SEQ * DDIM];
__device__ float g_v[BATCH * SEQ * CDIM];

// ---- helpers ----
__device__ __forceinline__ unsigned long long pack2(float lo, float hi) {
    unsigned long long r;
    asm("mov.b64 %0, {%1, %2};" : "=l"(r) : "f"(lo), "f"(hi));
    return r;
}
__device__ __forceinline__ void unpack2(unsigned long long v, float& lo, float& hi) {
    asm("mov.b64 {%0, %1}, %2;" : "=f"(lo), "=f"(hi) : "l"(v));
}
__device__ __forceinline__ unsigned long long ffma2(unsigned long long a, unsigned long long b,
                                                    unsigned long long c) {
    unsigned long long d;
    asm("fma.rn.f32x2 %0, %1, %2, %3;" : "=l"(d) : "l"(a), "l"(b), "l"(c));
    return d;
}
__device__ __forceinline__ uint32_t smem_u32(const void* p) {
    uint32_t a;
    asm("{ .reg .u64 t; cvta.to.shared.u64 t, %1; cvt.u32.u64 %0, t; }" : "=r"(a) : "l"(p));
    return a;
}
__device__ __forceinline__ void cp_async16(uint32_t dst, const void* src) {
    asm volatile("cp.async.cg.shared.global [%0], [%1], 16;" :: "r"(dst), "l"(src));
}
__device__ __forceinline__ uint32_t to_tf32(float f) {
    uint32_t u;
    asm("cvt.rna.tf32.f32 %0, %1;" : "=r"(u) : "f"(f));
    return u;
}
__device__ __forceinline__ float trunc13(float x) {
    return __uint_as_float(__float_as_uint(x) & 0xFFFFE000u);
}
__device__ __forceinline__ void mma8(float d[4], uint32_t a0, uint32_t a1, uint32_t a2,
                                     uint32_t a3, uint32_t b0, uint32_t b1) {
    asm volatile(
        "mma.sync.aligned.m16n8k8.row.col.f32.tf32.tf32.f32 "
        "{%0,%1,%2,%3}, {%4,%5,%6,%7}, {%8,%9}, {%0,%1,%2,%3};"
        : "+f"(d[0]), "+f"(d[1]), "+f"(d[2]), "+f"(d[3])
        : "r"(a0), "r"(a1), "r"(a2), "r"(a3), "r"(b0), "r"(b1));
}

// ---- smem byte offsets for flash kernel ----
#define OFF_QHI 0
#define OFF_QLO 16384
#define OFF_KTH 32768
#define OFF_KTL 40960
#define OFF_P   49152
#define OFF_V   81920       /* 2 x 65536 */
#define OFF_L   212992
#define OFF_LP  213504
#define FLASH_SMEM 215552

// k-dimension interleave within 8-blocks: pairs (k, k+4) -> adjacent words
__device__ __forceinline__ int intl8(int k) {
    return (k & ~7) | ((k & 3) << 1) | ((k >> 2) & 1);
}
// word indices (interleave + XOR swizzle, conflict-free per half-warp phase)
__device__ __forceinline__ int pQ(int r, int k)  { return r * 32 + (intl8(k) ^ ((r & 3) << 3)); }
__device__ __forceinline__ int pKT(int key, int d){ return key * 32 + (intl8(d) ^ ((key & 3) << 3)); }
__device__ __forceinline__ int pP(int r, int c)  { return r * 64 + (intl8(c) ^ ((r & 3) << 3)); }
__device__ __forceinline__ int pV(int k, int n)  { return k * 256 + (n ^ ((k & 3) * 8)); }

// ============================================================================
// Flash attention on mma.sync tf32 (split-compensated QK^T, no-max softmax)
// 256 threads = 8 warps: mw = wid&1 (64 rows), nw = wid>>1 (64 PV cols / 16 keys)
// ============================================================================
__global__ __launch_bounds__(256, 1)
void flash_mma(const float* __restrict__ Qg, const float* __restrict__ Kg,
               const float* __restrict__ Vg, const float* __restrict__ X,
               float* __restrict__ Out) {
    extern __shared__ char smem[];
    float*    sQh  = (float*)(smem + OFF_QHI);
    float*    sQl  = (float*)(smem + OFF_QLO);
    float*    sKTh = (float*)(smem + OFF_KTH);
    float*    sKTl = (float*)(smem + OFF_KTL);
    uint32_t* sPu  = (uint32_t*)(smem + OFF_P);
    uint32_t* sVu  = (uint32_t*)(smem + OFF_V);
    float*    sL   = (float*)(smem + OFF_L);
    float*    sLp  = (float*)(smem + OFF_LP);
    const uint32_t sb = smem_u32(smem);

    const int tid  = threadIdx.x;
    const int lane = tid & 31;
    const int wid  = tid >> 5;
    const int mw   = wid & 1;
    const int nw   = wid >> 1;
    const int g    = lane >> 2;
    const int l4   = lane & 3;
    const int b    = blockIdx.y;
    const int q0   = blockIdx.x * TQ;

    const float* Qb = Qg + ((size_t)b * SEQ + q0) * DDIM;
    const float* Kb = Kg + (size_t)b * SEQ * DDIM;
    const float* Vb = Vg + (size_t)b * SEQ * CDIM;

    // ---- prologue ----
    if (tid < 128) sL[tid] = 0.0f;
    // Q hi/lo split into interleaved layout
#pragma unroll
    for (int i = 0; i < 4; i++) {
        int idx = tid + i * 256;
        int r = idx >> 3, d4 = idx & 7;
        float4 v = *(const float4*)(Qb + r * DDIM + d4 * 4);
        float hv[4] = {trunc13(v.x), trunc13(v.y), trunc13(v.z), trunc13(v.w)};
        float lv[4] = {v.x - hv[0], v.y - hv[1], v.z - hv[2], v.w - hv[3]};
#pragma unroll
        for (int j = 0; j < 4; j++) {
            int w = pQ(r, d4 * 4 + j);
            sQh[w] = hv[j];
            sQl[w] = __uint_as_float(to_tf32(lv[j]));
        }
    }
    // K(0) -> KT smem [key][d'] interleaved
#pragma unroll
    for (int i = 0; i < 2; i++) {
        int idx = tid + i * 256;
        int key = idx >> 3, d4 = idx & 7;
        float4 v = *(const float4*)(Kb + key * DDIM + d4 * 4);
        float hv[4] = {trunc13(v.x), trunc13(v.y), trunc13(v.z), trunc13(v.w)};
        float lv[4] = {v.x - hv[0], v.y - hv[1], v.z - hv[2], v.w - hv[3]};
#pragma unroll
        for (int j = 0; j < 4; j++) {
            int w = pKT(key, d4 * 4 + j);
            sKTh[w] = hv[j];
            sKTl[w] = __uint_as_float(to_tf32(lv[j]));
        }
    }
    // V(0) cp.async
#pragma unroll
    for (int i = 0; i < 16; i++) {
        int f = tid + i * 256;
        int key = f >> 6, n4 = f & 63;
        uint32_t dst = sb + OFF_V + (uint32_t)pV(key, n4 * 4) * 4u;
        cp_async16(dst, Vb + (size_t)key * CDIM + n4 * 4);
    }
    asm volatile("cp.async.commit_group;" ::: "memory");
    __syncthreads();

    float oa[4][8][4];
#pragma unroll
    for (int mt = 0; mt < 4; mt++)
#pragma unroll
        for (int nt = 0; nt < 8; nt++)
#pragma unroll
            for (int c = 0; c < 4; c++) oa[mt][nt][c] = 0.0f;

#pragma unroll 1
    for (int t = 0; t < NT_TILES; t++) {
        const int buf = t & 1;
        const bool have_next = (t + 1 < NT_TILES);

        // 1. V(t) ready
        asm volatile("cp.async.wait_group 0;" ::: "memory");

        // 2. prefetch V(t+1)
        if (have_next) {
            const float* Vs = Vb + (size_t)(t + 1) * TK * CDIM;
            uint32_t vb0 = sb + OFF_V + (uint32_t)(1 - buf) * 65536u;
#pragma unroll
            for (int i = 0; i < 16; i++) {
                int f = tid + i * 256;
                int key = f >> 6, n4 = f & 63;
                cp_async16(vb0 + (uint32_t)pV(key, n4 * 4) * 4u, Vs + (size_t)key * CDIM + n4 * 4);
            }
            asm volatile("cp.async.commit_group;" ::: "memory");
        }
        // 3. stage K(t+1)
        float4 kreg[2];
        if (have_next) {
            const float* Ks = Kb + (size_t)(t + 1) * TK * DDIM;
#pragma unroll
            for (int i = 0; i < 2; i++) {
                int idx = tid + i * 256;
                kreg[i] = *(const float4*)(Ks + (idx >> 3) * DDIM + (idx & 7) * 4);
            }
        }

        // 4. S = QK^T (compensated tf32), LDS.64 fragment loads
        float sa[4][2][4];
#pragma unroll
        for (int mt = 0; mt < 4; mt++)
#pragma unroll
            for (int nt = 0; nt < 2; nt++)
#pragma unroll
                for (int c = 0; c < 4; c++) sa[mt][nt][c] = 0.0f;

#pragma unroll
        for (int ks = 0; ks < 4; ks++) {
            const int k0 = ks * 8;
            uint2 bh[2], bl[2];
#pragma unroll
            for (int nt = 0; nt < 2; nt++) {
                int key = nw * 16 + nt * 8 + g;
                bh[nt] = *(const uint2*)((const uint32_t*)sKTh + pKT(key, k0 + l4));
                bl[nt] = *(const uint2*)((const uint32_t*)sKTl + pKT(key, k0 + l4));
            }
#pragma unroll
            for (int mt = 0; mt < 4; mt++) {
                int r0 = mw * 64 + mt * 16 + g;
                uint2 qh0 = *(const uint2*)((const uint32_t*)sQh + pQ(r0, k0 + l4));
                uint2 qh1 = *(const uint2*)((const uint32_t*)sQh + pQ(r0 + 8, k0 + l4));
                uint2 ql0 = *(const uint2*)((const uint32_t*)sQl + pQ(r0, k0 + l4));
                uint2 ql1 = *(const uint2*)((const uint32_t*)sQl + pQ(r0 + 8, k0 + l4));
#pragma unroll
                for (int nt = 0; nt < 2; nt++) {
                    mma8(sa[mt][nt], qh0.x, qh1.x, qh0.y, qh1.y, bh[nt].x, bh[nt].y);
                    mma8(sa[mt][nt], qh0.x, qh1.x, qh0.y, qh1.y, bl[nt].x, bl[nt].y);
                    mma8(sa[mt][nt], ql0.x, ql1.x, ql0.y, ql1.y, bh[nt].x, bh[nt].y);
                }
            }
        }

        // 5. exp (no max), P -> smem (tf32, interleaved), partial row sums
#pragma unroll
        for (int mt = 0; mt < 4; mt++) {
            int r0 = mw * 64 + mt * 16 + g;
            float s0 = 0.0f, s1 = 0.0f;
#pragma unroll
            for (int nt = 0; nt < 2; nt++) {
                int col = nw * 16 + nt * 8 + l4 * 2;
                uint32_t e0 = to_tf32(__expf(sa[mt][nt][0]));
                uint32_t e1 = to_tf32(__expf(sa[mt][nt][1]));
                uint32_t e2 = to_tf32(__expf(sa[mt][nt][2]));
                uint32_t e3 = to_tf32(__expf(sa[mt][nt][3]));
                s0 += __uint_as_float(e0) + __uint_as_float(e1);
                s1 += __uint_as_float(e2) + __uint_as_float(e3);
                sPu[pP(r0, col)]     = e0;
                sPu[pP(r0, col + 1)] = e1;
                sPu[pP(r0 + 8, col)]     = e2;
                sPu[pP(r0 + 8, col + 1)] = e3;
            }
            s0 += __shfl_xor_sync(0xffffffffu, s0, 1);
            s0 += __shfl_xor_sync(0xffffffffu, s0, 2);
            s1 += __shfl_xor_sync(0xffffffffu, s1, 1);
            s1 += __shfl_xor_sync(0xffffffffu, s1, 2);
            if (l4 == 0) {
                sLp[nw * 128 + r0] = s0;
                sLp[nw * 128 + r0 + 8] = s1;
            }
        }
        __syncthreads();   // sync1: sP/sLp visible, KT free, V(t) visible

        // 7. KT(t+1) store + l accumulate
        if (have_next) {
#pragma unroll
            for (int i = 0; i < 2; i++) {
                int idx = tid + i * 256;
                int key = idx >> 3, d4 = idx & 7;
                float4 v = kreg[i];
                float hv[4] = {trunc13(v.x), trunc13(v.y), trunc13(v.z), trunc13(v.w)};
                float lv[4] = {v.x - hv[0], v.y - hv[1], v.z - hv[2], v.w - hv[3]};
#pragma unroll
                for (int j = 0; j < 4; j++) {
                    int w = pKT(key, d4 * 4 + j);
                    sKTh[w] = hv[j];
                    sKTl[w] = __uint_as_float(to_tf32(lv[j]));
                }
            }
        }
        if (tid < 128)
            sL[tid] += (sLp[tid] + sLp[128 + tid]) + (sLp[256 + tid] + sLp[384 + tid]);

        // 8. O += P @ V (P-frags via LDS.64)
        const uint32_t* sVb = sVu + (size_t)buf * 16384;
#pragma unroll
        for (int ks = 0; ks < 8; ks++) {
            const int k0 = ks * 8;
            uint2 pa0[4], pa1[4];
#pragma unroll
            for (int mt = 0; mt < 4; mt++) {
                int r0 = mw * 64 + mt * 16 + g;
                pa0[mt] = *(const uint2*)(sPu + pP(r0, k0 + l4));
                pa1[mt] = *(const uint2*)(sPu + pP(r0 + 8, k0 + l4));
            }
#pragma unroll
            for (int nt = 0; nt < 8; nt++) {
                int n = nw * 64 + nt * 8 + g;
                uint32_t b0 = sVb[pV(k0 + l4, n)];
                uint32_t b1 = sVb[pV(k0 + 4 + l4, n)];
#pragma unroll
                for (int mt = 0; mt < 4; mt++)
                    mma8(oa[mt][nt], pa0[mt].x, pa1[mt].x, pa0[mt].y, pa1[mt].y, b0, b1);
            }
        }
        __syncthreads();   // sync2
    }

    // ---- epilogue: O/l + residual ----
#pragma unroll
    for (int mt = 0; mt < 4; mt++) {
        int r0 = mw * 64 + mt * 16 + g;
        float inv0 = 1.0f / sL[r0];
        float inv1 = 1.0f / sL[r0 + 8];
        size_t row0 = (size_t)b * SEQ + q0 + r0;
#pragma unroll
        for (int nt = 0; nt < 8; nt++) {
            int col = nw * 64 + nt * 8 + l4 * 2;
            const float2* x0 = (const float2*)(X + (row0)*CDIM + col);
            const float2* x1 = (const float2*)(X + (row0 + 8) * CDIM + col);
            float2 xv0 = *x0, xv1 = *x1;
            float2 o0, o1;
            o0.x = oa[mt][nt][0] * inv0 + xv0.x;
            o0.y = oa[mt][nt][1] * inv0 + xv0.y;
            o1.x = oa[mt][nt][2] * inv1 + xv1.x;
            o1.y = oa[mt][nt][3] * inv1 + xv1.y;
            *(float2*)(Out + (row0)*CDIM + col) = o0;
            *(float2*)(Out + (row0 + 8) * CDIM + col) = o1;
        }
    }
}

// ============================================================================
// Merged q+k projection: Y{q,k}[M,32] = A[M,256] @ W{q,k}[256,32] + b{q,k}
// BM=64, BK=16, 128 threads; shares the A-tile between both outputs.
// ============================================================================
__global__ __launch_bounds__(128)
void sgemm_qk(const float* __restrict__ A,
              const float* __restrict__ Wq, const float* __restrict__ bq,
              const float* __restrict__ Wk, const float* __restrict__ bk,
              float* __restrict__ Yq, float* __restrict__ Yk) {
    constexpr int BM = 64, BK = 16, BN = 32, TM = 4, TN = 4, TX = 8, NT = 128;
    __shared__ float As[BK][BM + 4];
    __shared__ float Bq[BK][BN];
    __shared__ float Bk[BK][BN];
    const int tid = threadIdx.x;
    const int tx = tid % TX, ty = tid / TX;
    const int m0 = blockIdx.x * BM;

    unsigned long long aq[TM][2], ak[TM][2];
#pragma unroll
    for (int i = 0; i < TM; i++) {
        aq[i][0] = aq[i][1] = 0ull;
        ak[i][0] = ak[i][1] = 0ull;
    }

    for (int k0 = 0; k0 < CDIM; k0 += BK) {
        for (int idx = tid; idx < BM * BK / 4; idx += NT) {
            int m = idx / (BK / 4), kq = idx % (BK / 4);
            float4 t4 = *(const float4*)(A + (size_t)(m0 + m) * CDIM + k0 + kq * 4);
            As[kq * 4 + 0][m] = t4.x; As[kq * 4 + 1][m] = t4.y;
            As[kq * 4 + 2][m] = t4.z; As[kq * 4 + 3][m] = t4.w;
        }
        for (int idx = tid; idx < BK * BN / 4; idx += NT) {
            int kk = idx / (BN / 4), nq = idx % (BN / 4);
            *(float4*)&Bq[kk][nq * 4] = *(const float4*)(Wq + (size_t)(k0 + kk) * DDIM + nq * 4);
            *(float4*)&Bk[kk][nq * 4] = *(const float4*)(Wk + (size_t)(k0 + kk) * DDIM + nq * 4);
        }
        __syncthreads();
#pragma unroll
        for (int kk = 0; kk < BK; kk++) {
            ulonglong2 bbq = *(const ulonglong2*)&Bq[kk][tx * TN];
            ulonglong2 bbk = *(const ulonglong2*)&Bk[kk][tx * TN];
#pragma unroll
            for (int i = 0; i < TM; i++) {
                float a = As[kk][ty * TM + i];
                unsigned long long a2 = pack2(a, a);
                aq[i][0] = ffma2(bbq.x, a2, aq[i][0]);
                aq[i][1] = ffma2(bbq.y, a2, aq[i][1]);
                ak[i][0] = ffma2(bbk.x, a2, ak[i][0]);
                ak[i][1] = ffma2(bbk.y, a2, ak[i][1]);
            }
        }
        __syncthreads();
    }
    float4 bq4 = *(const float4*)(bq + tx * TN);
    float4 bk4 = *(const float4*)(bk + tx * TN);
#pragma unroll
    for (int i = 0; i < TM; i++) {
        int m = m0 + ty * TM + i;
        float v0, v1, v2, v3;
        unpack2(aq[i][0], v0, v1);
        unpack2(aq[i][1], v2, v3);
        float4 o;
        o.x = v0 + bq4.x; o.y = v1 + bq4.y; o.z = v2 + bq4.z; o.w = v3 + bq4.w;
        *(float4*)(Yq + (size_t)m * DDIM + tx * TN) = o;
        unpack2(ak[i][0], v0, v1);
        unpack2(ak[i][1], v2, v3);
        o.x = v0 + bk4.x; o.y = v1 + bk4.y; o.z = v2 + bk4.z; o.w = v3 + bk4.w;
        *(float4*)(Yk + (size_t)m * DDIM + tx * TN) = o;
    }
}

// ============================================================================
// V projection GEMM (round-2, passing)
// ============================================================================
template<int BM, int BN, int BK, int TM, int TN>
__global__ void sgemm_bias_kernel(const float* __restrict__ A, const float* __restrict__ W,
                                  const float* __restrict__ bias, float* __restrict__ Y,
                                  int M, int Kd, int N) {
    __shared__ float As[BK][BM + 4];
    __shared__ float Bs[BK][BN];
    constexpr int TX = BN / TN;
    constexpr int NT = (BM / TM) * TX;
    const int tid = threadIdx.x;
    const int tx = tid % TX, ty = tid / TX;
    const int m0 = blockIdx.x * BM, n0 = blockIdx.y * BN;

    unsigned long long acc[TM][2];
#pragma unroll
    for (int i = 0; i < TM; i++) { acc[i][0] = 0ull; acc[i][1] = 0ull; }

    for (int k0 = 0; k0 < Kd; k0 += BK) {
        for (int idx = tid; idx < BM * BK / 4; idx += NT) {
            int m = idx / (BK / 4), kq = idx % (BK / 4);
            float4 t4 = *(const float4*)(A + (size_t)(m0 + m) * Kd + k0 + kq * 4);
            As[kq * 4 + 0][m] = t4.x; As[kq * 4 + 1][m] = t4.y;
            As[kq * 4 + 2][m] = t4.z; As[kq * 4 + 3][m] = t4.w;
        }
        for (int idx = tid; idx < BK * BN / 4; idx += NT) {
            int kk = idx / (BN / 4), nq = idx % (BN / 4);
            *(float4*)&Bs[kk][nq * 4] = *(const float4*)(W + (size_t)(k0 + kk) * N + n0 + nq * 4);
        }
        __syncthreads();
#pragma unroll
        for (int kk = 0; kk < BK; kk++) {
            ulonglong2 bb = *(const ulonglong2*)&Bs[kk][tx * TN];
#pragma unroll
            for (int i = 0; i < TM; i++) {
                float a = As[kk][ty * TM + i];
                unsigned long long a2 = pack2(a, a);
                acc[i][0] = ffma2(bb.x, a2, acc[i][0]);
                acc[i][1] = ffma2(bb.y, a2, acc[i][1]);
            }
        }
        __syncthreads();
    }
    float4 bv4 = *(const float4*)(bias + n0 + tx * TN);
#pragma unroll
    for (int i = 0; i < TM; i++) {
        int m = m0 + ty * TM + i;
        float v0, v1, v2, v3;
        unpack2(acc[i][0], v0, v1);
        unpack2(acc[i][1], v2, v3);
        float4 o;
        o.x = v0 + bv4.x; o.y = v1 + bv4.y; o.z = v2 + bv4.z; o.w = v3 + bv4.w;
        *(float4*)(Y + (size_t)m * N + n0 + tx * TN) = o;
    }
}

// ============================================================================
extern "C" void kernel_launch(void* const* d_in, const int* in_sizes, int n_in,
                              void* d_out, int out_size) {
    const float* x  = (const float*)d_in[0];
    const float* wq = (const float*)d_in[1];
    const float* bq = (const float*)d_in[2];
    const float* wk = (const float*)d_in[3];
    const float* bk = (const float*)d_in[4];
    const float* wv = (const float*)d_in[5];
    const float* bv = (const float*)d_in[6];
    float* out = (float*)d_out;

    float *qp, *kp, *vp;
    cudaGetSymbolAddress((void**)&qp, g_q);
    cudaGetSymbolAddress((void**)&kp, g_k);
    cudaGetSymbolAddress((void**)&vp, g_v);

    {
        dim3 g(BATCH * SEQ / 64, 1);
        sgemm_qk<<<g, 128>>>(x, wq, bq, wk, bk, qp, kp);
    }
    {
        dim3 g(BATCH * SEQ / 128, CDIM / 64);
        sgemm_bias_kernel<128, 64, 16, 8, 4><<<g, 256>>>(x, wv, bv, vp, BATCH * SEQ, CDIM, CDIM);
    }
    {
        cudaFuncSetAttribute(flash_mma, cudaFuncAttributeMaxDynamicSharedMemorySize, FLASH_SMEM);
        dim3 g(SEQ / TQ, BATCH);
        flash_mma<<<g, 256, FLASH_SMEM>>>(qp, kp, vp, x, out);
    }
}